// round 8
// baseline (speedup 1.0000x reference)
#include <cuda_runtime.h>
#include <cstdint>

#define NUM_ANCHORS 145152
#define NUM_CH 85
#define INV_IMG (1.0f / 1536.0f)
#define ROWS_PER_TILE 8
#define WARPS_PER_BLOCK 8
#define THREADS (WARPS_PER_BLOCK * 32)
#define NUM_TILES (NUM_ANCHORS / ROWS_PER_TILE)        // 18144
#define TILE_FLOATS (ROWS_PER_TILE * NUM_CH)           // 680
#define TILE_F4 (TILE_FLOATS / 4)                      // 170
#define BUF_FLOATS (2 * TILE_FLOATS)                   // per-warp double buffer
#define SMEM_BYTES (WARPS_PER_BLOCK * BUF_FLOATS * 4)  // 43520 B

// d_out layout (fp32), reference tuple order, flattened:
//   [0 .. 4N)    bboxes     (N,4) = x0, y0, x1, y1
//   [4N .. 5N)   scores     (N,)
//   [5N .. 6N)   class_pred (N,)  (as float)
//   [6N .. 12N)  detections (N,6) = x0, y0, x1, y1, conf, cls

typedef unsigned long long u64;

__device__ __forceinline__ unsigned smem_u32(const void* p) {
    unsigned a;
    asm("{ .reg .u64 t; cvta.to.shared.u64 t, %1; cvt.u32.u64 %0, t; }"
        : "=r"(a) : "l"(p));
    return a;
}

__device__ __forceinline__ void cp_async16(unsigned dst, const void* src) {
    asm volatile("cp.async.cg.shared.global [%0], [%1], 16;"
                 :: "r"(dst), "l"(src));
}

// Stage one 8-row tile (2720 B = 170 float4, contiguous) per warp.
__device__ __forceinline__ void issue_tile_load(unsigned dst0,
                                                const float* __restrict__ pred,
                                                int tile, int lane)
{
    const float4* src = (const float4*)(pred + (long long)tile * TILE_FLOATS);
    #pragma unroll
    for (int j = 0; j < TILE_F4 / 32; ++j)           // 5 full rounds
        cp_async16(dst0 + (lane + j * 32) * 16, src + lane + j * 32);
    if (lane < TILE_F4 - (TILE_F4 / 32) * 32)        // remainder: 10 lanes
        cp_async16(dst0 + (lane + (TILE_F4 / 32) * 32) * 16,
                   src + lane + (TILE_F4 / 32) * 32);
    asm volatile("cp.async.commit_group;");
}

// Pack (value, channel) so u64 max == argmax with lowest-index tie-break.
// Valid because predictions >= 0: positive-float bits are order-isomorphic.
__device__ __forceinline__ u64 pack_key(float v, int ch) {
    return ((u64)__float_as_uint(v) << 32) | (unsigned)(255 - ch);
}

// Log-depth max over 10 keys.
__device__ __forceinline__ u64 tree10(const u64* k) {
    u64 a0 = k[0] > k[1] ? k[0] : k[1];
    u64 a1 = k[2] > k[3] ? k[2] : k[3];
    u64 a2 = k[4] > k[5] ? k[4] : k[5];
    u64 a3 = k[6] > k[7] ? k[6] : k[7];
    u64 a4 = k[8] > k[9] ? k[8] : k[9];
    u64 b0 = a0 > a1 ? a0 : a1;
    u64 b1 = a2 > a3 ? a2 : a3;
    u64 c0 = b0 > b1 ? b0 : b1;
    return c0 > a4 ? c0 : a4;
}

__device__ __forceinline__ u64 shfl_xor_u64(u64 v, int off) {
    const unsigned FULL = 0xffffffffu;
    unsigned lo = (unsigned)v, hi = (unsigned)(v >> 32);
    lo = __shfl_xor_sync(FULL, lo, off);
    hi = __shfl_xor_sync(FULL, hi, off);
    return ((u64)hi << 32) | lo;
}

__device__ __forceinline__ void compute_tile(const float* __restrict__ s_base,
                                             float* __restrict__ out,
                                             int tile, int lane)
{
    const int row = lane >> 2;           // 0..7
    const int q   = lane & 3;            // quarter-lane within the row group
    const float* s = s_base + row * NUM_CH;   // all 4 group lanes: SAME row
    const int anchor = tile * ROWS_PER_TILE + row;

    // Header (broadcast reads — group lanes hit identical addresses).
    float cx  = s[0];
    float cy  = s[1];
    float w   = s[2];
    float h   = s[3];
    float obj = s[4];

    // Lane q covers channels [20q .. 20q+19]; two 10-key trees + combine.
    const int ch0 = 20 * q;
    const float* cs = s + 5 + ch0;

    u64 ka[10], kb[10];
    #pragma unroll
    for (int k = 0; k < 10; ++k)  ka[k] = pack_key(cs[k],      ch0 + k);
    #pragma unroll
    for (int k = 0; k < 10; ++k)  kb[k] = pack_key(cs[10 + k], ch0 + 10 + k);

    u64 kmax_a = tree10(ka);
    u64 kmax_b = tree10(kb);
    u64 key = kmax_a > kmax_b ? kmax_a : kmax_b;

    // Combine the four quarters (packed key: max == lowest-index tie-break).
    #pragma unroll
    for (int off = 1; off <= 2; off <<= 1) {
        u64 o = shfl_xor_u64(key, off);
        key = o > key ? o : key;
    }

    float bv = __uint_as_float((unsigned)(key >> 32));
    int   bi = 255 - (int)(key & 0xffu);

    float bx = cx * INV_IMG;
    float by = cy * INV_IMG;
    float bw = w  * INV_IMG;
    float bh = h  * INV_IMG;
    float x0 = bx - bw * 0.5f;
    float y0 = by - bh * 0.5f;
    float x1 = bx + bw * 0.5f;
    float y1 = by + bh * 0.5f;

    float conf  = bv;
    float clsf  = (float)bi;
    float score = obj * conf;

    float* out_sc  = out + (long long)NUM_ANCHORS * 4;
    float* out_cls = out + (long long)NUM_ANCHORS * 5;
    float* out_det = out + (long long)NUM_ANCHORS * 6;

    // Distribute writes across the 4 group lanes; every stream coalesced.
    if (q == 0) {
        ((float4*)out)[anchor] = make_float4(x0, y0, x1, y1);
    } else if (q == 1) {
        out_sc[anchor]  = score;
        out_cls[anchor] = clsf;
    } else {
        float2* det = (float2*)(out_det + (long long)anchor * 6);
        if (q == 2) {
            det[0] = make_float2(x0, y0);
            det[1] = make_float2(x1, y1);
        } else {
            det[2] = make_float2(conf, clsf);
        }
    }
}

__global__ __launch_bounds__(THREADS, 5)
void yolo_decode_kernel(const float* __restrict__ pred,
                        float* __restrict__ out,
                        int n_warps_total)
{
    extern __shared__ float smem[];

    const int warp = threadIdx.x >> 5;
    const int lane = threadIdx.x & 31;
    const int wgid = blockIdx.x * WARPS_PER_BLOCK + warp;

    float* buf0 = smem + warp * BUF_FLOATS;
    float* buf1 = buf0 + TILE_FLOATS;
    unsigned dsts[2] = { smem_u32(buf0), smem_u32(buf1) };
    float*   bufs[2] = { buf0, buf1 };

    int tile = wgid;
    if (tile >= NUM_TILES) return;

    issue_tile_load(dsts[0], pred, tile, lane);

    int cur = 0;
    int next_tile = tile + n_warps_total;

    while (true) {
        if (next_tile < NUM_TILES) {
            issue_tile_load(dsts[cur ^ 1], pred, next_tile, lane);
            asm volatile("cp.async.wait_group 1;");
        } else {
            asm volatile("cp.async.wait_group 0;");
        }
        __syncwarp();

        compute_tile(bufs[cur], out, tile, lane);

        if (next_tile >= NUM_TILES) break;
        cur ^= 1;
        tile = next_tile;
        next_tile += n_warps_total;
    }
}

extern "C" void kernel_launch(void* const* d_in, const int* in_sizes, int n_in,
                              void* d_out, int out_size)
{
    const float* pred = (const float*)d_in[0];
    // d_in[1] = score_threshold — unused by the reference computation.
    float* out = (float*)d_out;

    cudaFuncSetAttribute(yolo_decode_kernel,
                         cudaFuncAttributeMaxDynamicSharedMemorySize,
                         SMEM_BYTES);

    const int blocks = 740;                        // 5 per SM, persistent
    const int n_warps = blocks * WARPS_PER_BLOCK;  // 5920
    yolo_decode_kernel<<<blocks, THREADS, SMEM_BYTES>>>(pred, out, n_warps);
}

// round 9
// speedup vs baseline: 1.2179x; 1.2179x over previous
#include <cuda_runtime.h>
#include <cstdint>

#define NUM_ANCHORS 145152
#define NUM_CH 85
#define INV_IMG (1.0f / 1536.0f)
#define ROWS_PER_TILE 16
#define WARPS_PER_BLOCK 8
#define THREADS (WARPS_PER_BLOCK * 32)
#define NUM_TILES (NUM_ANCHORS / ROWS_PER_TILE)        // 9072
#define TILE_FLOATS (ROWS_PER_TILE * NUM_CH)           // 1360
#define TILE_F4 (TILE_FLOATS / 4)                      // 340
#define BUF_FLOATS (2 * TILE_FLOATS)                   // per-warp double buffer
#define SMEM_BYTES (WARPS_PER_BLOCK * BUF_FLOATS * 4)  // 87040 B

// d_out layout (fp32), reference tuple order, flattened:
//   [0 .. 4N)    bboxes     (N,4) = x0, y0, x1, y1
//   [4N .. 5N)   scores     (N,)
//   [5N .. 6N)   class_pred (N,)  (as float)
//   [6N .. 12N)  detections (N,6) = x0, y0, x1, y1, conf, cls

__device__ __forceinline__ unsigned smem_u32(const void* p) {
    unsigned a;
    asm("{ .reg .u64 t; cvta.to.shared.u64 t, %1; cvt.u32.u64 %0, t; }"
        : "=r"(a) : "l"(p));
    return a;
}

__device__ __forceinline__ void cp_async16(unsigned dst, const void* src) {
    asm volatile("cp.async.cg.shared.global [%0], [%1], 16;"
                 :: "r"(dst), "l"(src));
}

// Stage one 16-row tile (5440 B = 340 float4, contiguous) per warp.
__device__ __forceinline__ void issue_tile_load(unsigned dst0,
                                                const float* __restrict__ pred,
                                                int tile, int lane)
{
    const float4* src = (const float4*)(pred + (long long)tile * TILE_FLOATS);
    #pragma unroll
    for (int j = 0; j < TILE_F4 / 32; ++j)           // 10 full rounds
        cp_async16(dst0 + (lane + j * 32) * 16, src + lane + j * 32);
    if (lane < TILE_F4 - (TILE_F4 / 32) * 32)        // remainder: 20 lanes
        cp_async16(dst0 + (lane + (TILE_F4 / 32) * 32) * 16,
                   src + lane + (TILE_F4 / 32) * 32);
    asm volatile("cp.async.commit_group;");
}

__device__ __forceinline__ void compute_tile(const float* __restrict__ s_base,
                                             float* __restrict__ out,
                                             int tile, int lane)
{
    const unsigned FULL = 0xffffffffu;
    const int row  = lane >> 1;               // 0..15
    const int half = lane & 1;
    const float* s = s_base + row * NUM_CH;   // both pair lanes: SAME row
    const int anchor = tile * ROWS_PER_TILE + row;

    // Header (both lanes read identical values from the shared row).
    float cx  = s[0];
    float cy  = s[1];
    float w   = s[2];
    float h   = s[3];
    float obj = s[4];

    // Lane covers 40 channels: even -> ch 0..39, odd -> ch 40..79.
    const int base = 40 * half;
    const float* cs = s + 5 + base;

    // Register-resident values: 40 independent LDS (pipelined by ptxas).
    float v[40];
    #pragma unroll
    for (int k = 0; k < 40; ++k) v[k] = cs[k];

    // Tournament tree, depth 6. Left operand always has the lower channel
    // index, so '>=' gives exact lowest-index-wins tie-break.
    float tv[20]; int ti[20];
    #pragma unroll
    for (int k = 0; k < 20; ++k) {
        bool p = v[2*k] >= v[2*k+1];
        tv[k] = p ? v[2*k] : v[2*k+1];
        ti[k] = p ? 2*k : 2*k+1;
    }
    #pragma unroll
    for (int k = 0; k < 10; ++k) {
        bool p = tv[2*k] >= tv[2*k+1];
        tv[k] = p ? tv[2*k] : tv[2*k+1];
        ti[k] = p ? ti[2*k] : ti[2*k+1];
    }
    #pragma unroll
    for (int k = 0; k < 5; ++k) {
        bool p = tv[2*k] >= tv[2*k+1];
        tv[k] = p ? tv[2*k] : tv[2*k+1];
        ti[k] = p ? ti[2*k] : ti[2*k+1];
    }
    bool p0 = tv[0] >= tv[1]; float a = p0 ? tv[0] : tv[1]; int ai = p0 ? ti[0] : ti[1];
    bool p1 = tv[2] >= tv[3]; float b = p1 ? tv[2] : tv[3]; int bj = p1 ? ti[2] : ti[3];
    bool p2 = a >= b;         float c = p2 ? a : b;         int ci = p2 ? ai : bj;
    bool p3 = c >= tv[4];     float bv = p3 ? c : tv[4];    int bl = p3 ? ci : ti[4];
    int bidx = base + bl;     // global channel index 0..79

    // Combine the two lane halves (lowest index wins ties).
    float ov = __shfl_xor_sync(FULL, bv, 1);
    int   oi = __shfl_xor_sync(FULL, bidx, 1);
    if (ov > bv || (ov == bv && oi < bidx)) { bv = ov; bidx = oi; }

    float bx = cx * INV_IMG;
    float by = cy * INV_IMG;
    float bw = w  * INV_IMG;
    float bh = h  * INV_IMG;
    float x0 = bx - bw * 0.5f;
    float y0 = by - bh * 0.5f;
    float x1 = bx + bw * 0.5f;
    float y1 = by + bh * 0.5f;

    float conf  = bv;
    float clsf  = (float)bidx;
    float score = obj * conf;

    float* out_sc  = out + (long long)NUM_ANCHORS * 4;
    float* out_cls = out + (long long)NUM_ANCHORS * 5;
    float* out_det = out + (long long)NUM_ANCHORS * 6;

    if (half == 0) {
        // 16 even lanes: contiguous float4 (256 B/warp) + scalar streams.
        ((float4*)out)[anchor] = make_float4(x0, y0, x1, y1);
        out_sc[anchor]  = score;
        out_cls[anchor] = clsf;
    } else {
        // 16 odd lanes: detections, 3x float2, 384 B contiguous per warp.
        float2* det = (float2*)(out_det + (long long)anchor * 6);
        det[0] = make_float2(x0, y0);
        det[1] = make_float2(x1, y1);
        det[2] = make_float2(conf, clsf);
    }
}

__global__ __launch_bounds__(THREADS)
void yolo_decode_kernel(const float* __restrict__ pred,
                        float* __restrict__ out,
                        int n_warps_total)
{
    extern __shared__ float smem[];

    const int warp = threadIdx.x >> 5;
    const int lane = threadIdx.x & 31;
    const int wgid = blockIdx.x * WARPS_PER_BLOCK + warp;

    float* buf0 = smem + warp * BUF_FLOATS;
    float* buf1 = buf0 + TILE_FLOATS;
    unsigned dsts[2] = { smem_u32(buf0), smem_u32(buf1) };
    float*   bufs[2] = { buf0, buf1 };

    int tile = wgid;
    if (tile >= NUM_TILES) return;

    // prologue: fill buffer 0
    issue_tile_load(dsts[0], pred, tile, lane);

    int cur = 0;
    int next_tile = tile + n_warps_total;

    while (true) {
        if (next_tile < NUM_TILES) {
            issue_tile_load(dsts[cur ^ 1], pred, next_tile, lane);
            asm volatile("cp.async.wait_group 1;");
        } else {
            asm volatile("cp.async.wait_group 0;");
        }
        __syncwarp();

        compute_tile(bufs[cur], out, tile, lane);

        if (next_tile >= NUM_TILES) break;
        cur ^= 1;
        tile = next_tile;
        next_tile += n_warps_total;
    }
}

extern "C" void kernel_launch(void* const* d_in, const int* in_sizes, int n_in,
                              void* d_out, int out_size)
{
    const float* pred = (const float*)d_in[0];
    // d_in[1] = score_threshold — unused by the reference computation.
    float* out = (float*)d_out;

    cudaFuncSetAttribute(yolo_decode_kernel,
                         cudaFuncAttributeMaxDynamicSharedMemorySize,
                         SMEM_BYTES);

    const int blocks = 296;                        // 2 per SM, persistent
    const int n_warps = blocks * WARPS_PER_BLOCK;  // 2368
    yolo_decode_kernel<<<blocks, THREADS, SMEM_BYTES>>>(pred, out, n_warps);
}